// round 11
// baseline (speedup 1.0000x reference)
#include <cuda_runtime.h>
#include <math.h>
#include <stdint.h>

#define NB    4
#define LSEQ  2054
#define LSEQT 2080
#define EE    512
#define HID   640
#define NHh   10
#define NC    527
#define MH    20
#define SNT   64
#define SNB   33
#define GRIDT (SNB*NB)      // 132 blocks, 1/SM
#define TTHR  512
#define FT_TILES 576        // 16 e-tiles x 9 n-tiles x 4 b
#define KQ_PAIRS 40         // 80 kq tiles, 2 per block
#define P_VIRT (FT_TILES + KQ_PAIRS)   // 616
#define P_ROUNDS 5          // ceil(616/132)
#define KPE (9.210340371976184f/512.0f)

typedef unsigned long long u64;

// ---------------- device scratch ----------------
__device__ __align__(128) float g_featsT[NB*EE*LSEQT];
__device__ u64   g_kq2[NB*256*MH];
__device__ float g_cb[NB*MH];
__device__ float g_mx  [SNB*NB*MH];
__device__ float g_denp[SNB*NB*MH];
__device__ float g_wfp [SNB*NB*MH*EE];
__device__ float g_pp[4*8*HID];
__device__ unsigned g_barc = 0;
__device__ volatile unsigned g_gen = 0;

// ---------------- grid barrier (all GRIDT blocks co-resident) -------------
__device__ __forceinline__ void gsync(){
  __syncthreads();
  if (threadIdx.x == 0){
    __threadfence();
    unsigned gen = g_gen;
    unsigned arrived = atomicAdd(&g_barc, 1u) + 1u;
    if (arrived % GRIDT == 0u){
      __threadfence();
      g_gen = gen + 1u;
    } else {
      while (g_gen == gen) { __nanosleep(64); }
    }
    __threadfence();
  }
  __syncthreads();
}

// ---------------- packed f32x2 helpers ----------------
__device__ __forceinline__ u64 pk2(float x, float y){
  u64 r; asm("mov.b64 %0,{%1,%2};" : "=l"(r) : "f"(x), "f"(y)); return r;
}
__device__ __forceinline__ float2 upk2(u64 v){
  float2 r; asm("mov.b64 {%0,%1},%2;" : "=f"(r.x), "=f"(r.y) : "l"(v)); return r;
}
__device__ __forceinline__ void fma2(u64 &d, u64 a, u64 b){
  asm("fma.rn.f32x2 %0,%1,%2,%0;" : "+l"(d) : "l"(a), "l"(b));
}
__device__ __forceinline__ u64 add2(u64 a, u64 b){
  u64 r; asm("add.rn.f32x2 %0,%1,%2;" : "=l"(r) : "l"(a), "l"(b)); return r;
}

__device__ __forceinline__ const float* row_src(int b, int n,
    const float* aud, const float* vid, const float* atok,
    const float* vtok, const float* btk){
  if (n < 1024)  return aud + ((size_t)b*1024 + n)*EE;
  if (n == 1024) return atok;
  if (n < 1029)  return btk + (size_t)(n-1025)*EE;
  if (n < 2053)  return vid + ((size_t)b*1024 + (n-1029))*EE;
  return vtok;
}

__device__ __forceinline__ float pe_val(int n, int e){
  float f = __expf(-(float)(e & ~1) * KPE);
  float a = (float)n * f;
  float q = rintf(a * 0.15915494309189535f);
  a = fmaf(q, -6.2831855f, a);
  a = fmaf(q, 1.7484556e-7f, a);
  float sn, cs; __sincosf(a, &sn, &cs);
  return (e & 1) ? cs : sn;
}

// ============ single persistent kernel: P -> A -> B -> C ============
// dyn smem 56,832 B. Phase P: s_t f[256][33] (33,792) or kq staging (6.5K).
// Phase A: [0,40960) s_kq u64[256][20] -> s_part f[8][64][20] -> s_comb;
//          [40960,46080) s_sc f[64][20]; [46080,56320) s_p u64[64][20];
//          [56320,56832) s_rp u64[64] (row pointers).
__global__ void __launch_bounds__(TTHR, 1) k_all(
    const float* __restrict__ aud, const float* __restrict__ vid,
    const float* __restrict__ atok, const float* __restrict__ vtok,
    const float* __restrict__ btk,
    const float* __restrict__ Wk,  const float* __restrict__ bk,
    const float* __restrict__ Wq,  const float* __restrict__ bq,
    const float* __restrict__ Wv,  const float* __restrict__ bv,
    const float* __restrict__ lng, const float* __restrict__ lnb,
    const float* __restrict__ Wap, const float* __restrict__ bap,
    const float* __restrict__ Wvp, const float* __restrict__ bvp,
    float* __restrict__ out){
  extern __shared__ __align__(16) char dyn[];
  int tid = threadIdx.x, blk = blockIdx.x;

  // ======== phase P: featsT tiles + kq pairs (virtualized) ========
  for (int r = 0; r < P_ROUNDS; r++){
    int v = r*GRIDT + blk;
    if (v < FT_TILES){
      float (*s_t)[33] = (float(*)[33])dyn;
      int et = v & 15, nt = (v >> 4) % 9, bz = v / 144;
      int lane = tid & 31, w = tid >> 5;      // 16 warps x 16 n each
      int e = et*32 + lane;
      float f = __expf(-(float)(e & ~1) * KPE);
      bool odd = e & 1;
      int n0 = nt*256 + w*16;
      float a = (float)n0 * f;
      float qr = rintf(a * 0.15915494309189535f);
      a = fmaf(qr, -6.2831855f, a);
      a = fmaf(qr, 1.7484556e-7f, a);
      float sn, cs; __sincosf(a, &sn, &cs);
      float sf, cf; __sincosf(f, &sf, &cf);
      #pragma unroll 4
      for (int j = 0; j < 16; j++){
        int n = n0 + j;
        float val = 0.f;
        if (n < LSEQ){
          const float* src = row_src(bz, n, aud, vid, atok, vtok, btk);
          val = src[e] + (odd ? cs : sn);
        }
        s_t[w*16 + j][lane] = val;
        float sn2 = fmaf(sn, cf,  cs*sf);
        float cs2 = fmaf(cs, cf, -sn*sf);
        sn = sn2; cs = cs2;
      }
      __syncthreads();
      #pragma unroll
      for (int i = 0; i < 16; i++){
        int task = (tid >> 5) + 16*i;         // 0..255 = 32 ee x 8 seg
        int ee = task >> 3, seg = task & 7;
        int n = nt*256 + seg*32 + lane;
        if (n < LSEQ)
          g_featsT[((size_t)bz*EE + et*32 + ee)*LSEQT + n] = s_t[seg*32 + lane][ee];
      }
    } else if (v < P_VIRT){
      int pairIdx = v - FT_TILES;
      int h = tid >> 8, tid2 = tid & 255;
      int blk2 = pairIdx*2 + h;
      int b = blk2 / MH, mh = blk2 % MH, m = mh / NHh, hh = mh % NHh;
      float* sf    = (float*)dyn + h*EE;           // [0,1024) floats
      float* spart = (float*)dyn + 1024 + h*256;   // [1024,1536)
      float* kk    = (float*)dyn + 1536 + h*64;    // [1536,1664)
      int nrow = m ? 1029 : 0;
      const float* srcb = m ? (vid + (size_t)b*1024*EE) : (aud + (size_t)b*1024*EE);
      for (int e = tid2; e < EE; e += 256)
        sf[e] = srcb[e] + pe_val(nrow, e);
      __syncthreads();
      {
        int col = tid2 & 63, eg = tid2 >> 6;
        const float* w_ = Wk + hh*64 + col;
        float p = 0.f;
        #pragma unroll 4
        for (int e = eg*128; e < eg*128 + 128; e++)
          p = fmaf(sf[e], w_[(size_t)e*HID], p);
        spart[eg*64 + col] = p;
      }
      __syncthreads();
      if (tid2 < 64)
        kk[tid2] = bk[hh*64 + tid2] + ((spart[tid2] + spart[64+tid2]) +
                                       (spart[128+tid2] + spart[192+tid2]));
      __syncthreads();
      if (tid2 == 0){
        float s2 = 0.f;
        for (int d = 0; d < 64; d++) s2 += kk[d]*bq[hh*64 + d];
        g_cb[blk2] = s2;
      }
      int e0 = tid2*2;
      const float4* w0 = (const float4*)(Wq + (size_t)e0*HID + hh*64);
      const float4* w1 = (const float4*)(Wq + (size_t)(e0+1)*HID + hh*64);
      float r0 = 0.f, r1 = 0.f;
      #pragma unroll
      for (int d4 = 0; d4 < 16; d4++){
        float4 a4 = w0[d4], c4 = w1[d4];
        float k0 = kk[4*d4], k1 = kk[4*d4+1], k2 = kk[4*d4+2], k3 = kk[4*d4+3];
        r0 = fmaf(k0,a4.x, fmaf(k1,a4.y, fmaf(k2,a4.z, fmaf(k3,a4.w, r0))));
        r1 = fmaf(k0,c4.x, fmaf(k1,c4.y, fmaf(k2,c4.z, fmaf(k3,c4.w, r1))));
      }
      g_kq2[((size_t)b*256 + tid2)*MH + mh] = pk2(r0, r1);
    }
    __syncthreads();
  }

  gsync();   // featsT + kq2 + cb ready

  // ======== phase A: attention ========
  {
    u64*  s_kq = (u64*)dyn;
    float (*s_part)[SNT][MH] = (float(*)[SNT][MH])dyn;
    float (*s_sc)[MH]        = (float(*)[MH])(dyn + 40960);
    u64   (*s_p)[MH]         = (u64(*)[MH])(dyn + 46080);
    u64*  s_comb             = (u64*)dyn;
    u64*  s_rp               = (u64*)(dyn + 56320);
    __shared__ float s_cb[MH], s_mx[MH];
    int c = blk % SNB, b = blk / SNB;
    int nbase = c*SNT;
    {
      const u64* src = g_kq2 + (size_t)b*256*MH;
      for (int i = tid; i < 256*MH; i += TTHR) s_kq[i] = src[i];
    }
    if (tid < MH) s_cb[tid] = g_cb[b*MH + tid];
    if (tid >= 256 && tid < 256 + SNT){
      int n = nbase + (tid - 256); if (n > LSEQ-1) n = LSEQ-1;
      s_rp[tid-256] = (u64)(size_t)row_src(b, n, aud, vid, atok, vtok, btk);
    }
    __syncthreads();
    int slot = tid & 63, esub = tid >> 6;
    int n = nbase + slot; if (n > LSEQ-1) n = LSEQ-1;
    const float* ft = g_featsT + ((size_t)b*EE + esub*64)*LSEQT + n;
    const u64* kqp = s_kq + (size_t)(esub*32)*MH;
    u64 acc[MH];
    #pragma unroll
    for (int q = 0; q < MH; q++) acc[q] = 0ull;
    #pragma unroll 4
    for (int ep = 0; ep < 32; ep++){
      float f0 = ft[(size_t)(2*ep  )*LSEQT];
      float f1 = ft[(size_t)(2*ep+1)*LSEQT];
      u64 f2 = pk2(f0, f1);
      const ulonglong2* kp2 = (const ulonglong2*)(kqp + (size_t)ep*MH);
      #pragma unroll
      for (int q2 = 0; q2 < 10; q2++){
        ulonglong2 kk2 = kp2[q2];
        fma2(acc[2*q2  ], f2, kk2.x);
        fma2(acc[2*q2+1], f2, kk2.y);
      }
    }
    __syncthreads();
    #pragma unroll
    for (int q = 0; q < MH; q++){
      float2 v2 = upk2(acc[q]);
      s_part[esub][slot][q] = v2.x + v2.y;
    }
    __syncthreads();
    for (int i = tid; i < SNT*MH; i += TTHR){
      int nl = i / MH, q = i % MH;
      float s = ((s_part[0][nl][q] + s_part[1][nl][q]) +
                 (s_part[2][nl][q] + s_part[3][nl][q])) +
                ((s_part[4][nl][q] + s_part[5][nl][q]) +
                 (s_part[6][nl][q] + s_part[7][nl][q]));
      s = (s + s_cb[q]) * 0.125f;
      s_sc[nl][q] = (nbase + nl < LSEQ) ? s : -1e30f;
    }
    __syncthreads();
    if (tid < 160){
      int q = tid >> 3, j = tid & 7;
      float mloc = -1e30f;
      #pragma unroll
      for (int nl = j*8; nl < j*8 + 8; nl++) mloc = fmaxf(mloc, s_sc[nl][q]);
      mloc = fmaxf(mloc, __shfl_xor_sync(0xffffffffu, mloc, 1));
      mloc = fmaxf(mloc, __shfl_xor_sync(0xffffffffu, mloc, 2));
      mloc = fmaxf(mloc, __shfl_xor_sync(0xffffffffu, mloc, 4));
      if (j == 0){ s_mx[q] = mloc; g_mx[(c*NB + b)*MH + q] = mloc; }
    }
    __syncthreads();
    for (int i = tid; i < SNT*MH; i += TTHR){
      int nl = i / MH, q = i % MH;
      float p = __expf(s_sc[nl][q] - s_mx[q]);
      s_p[nl][q] = pk2(p, p);
    }
    __syncthreads();
    if (tid < 160){
      int q = tid >> 3, j = tid & 7;
      float d = 0.f;
      #pragma unroll
      for (int nl = j*8; nl < j*8 + 8; nl++) d += *(const float*)&s_p[nl][q];
      d += __shfl_xor_sync(0xffffffffu, d, 1);
      d += __shfl_xor_sync(0xffffffffu, d, 2);
      d += __shfl_xor_sync(0xffffffffu, d, 4);
      if (j == 0) g_denp[(c*NB + b)*MH + q] = d;
    }
    // ---- weighted feats from RAW inputs + pe rotation recurrence ----
    int half = tid >> 8, ep0 = tid & 255;
    int e0 = ep0*2;
    int nv = LSEQ - nbase; if (nv > SNT) nv = SNT;
    int nlo = half*32;
    int nhi = nv < (half+1)*32 ? nv : (half+1)*32;
    float fe = __expf(-(float)e0 * KPE);
    float a = (float)(nbase + nlo) * fe;
    float qr = rintf(a * 0.15915494309189535f);
    a = fmaf(qr, -6.2831855f, a);
    a = fmaf(qr, 1.7484556e-7f, a);
    float sn, cs; __sincosf(a, &sn, &cs);
    float sfe, cfe; __sincosf(fe, &sfe, &cfe);
    u64 acc2[MH];
    #pragma unroll
    for (int q = 0; q < MH; q++) acc2[q] = 0ull;
    #pragma unroll 2
    for (int nl = nlo; nl < nhi; nl++){
      const float* srcp = (const float*)(size_t)s_rp[nl] + e0;
      u64 f = add2(*(const u64*)srcp, pk2(sn, cs));
      const ulonglong2* pp2 = (const ulonglong2*)s_p[nl];
      #pragma unroll
      for (int q2 = 0; q2 < 10; q2++){
        ulonglong2 pk = pp2[q2];
        fma2(acc2[2*q2  ], pk.x, f);
        fma2(acc2[2*q2+1], pk.y, f);
      }
      float sn2 = fmaf(sn, cfe,  cs*sfe);
      float cs2 = fmaf(cs, cfe, -sn*sfe);
      sn = sn2; cs = cs2;
    }
    if (half == 1){
      #pragma unroll
      for (int q = 0; q < MH; q++) s_comb[ep0*MH + q] = acc2[q];
    }
    __syncthreads();
    if (half == 0){
      float* dst = g_wfp + ((size_t)(c*NB + b)*MH)*EE + e0;
      #pragma unroll
      for (int q = 0; q < MH; q++){
        float2 v2 = upk2(add2(acc2[q], s_comb[ep0*MH + q]));
        *(float2*)(dst + (size_t)q*EE) = v2;
      }
    }
  }

  gsync();

  // ======== phase B: flash-combine + partial Wv proj (blocks 0..31) ========
  if (blk < 32){
    float (*s_mxp)[SNB+1]   = (float(*)[SNB+1])dyn;
    float (*s_scale)[SNB+1] = (float(*)[SNB+1])(dyn + 1360);
    float* s_m   = (float*)(dyn + 2720);
    float* s_inv = (float*)(dyn + 2784);
    float (*s_wf)[128] = (float(*)[128])(dyn + 2848);
    int bm = blk >> 2, es = blk & 3;
    int b = bm >> 1, m = bm & 1, q0 = m*NHh;
    for (int i = tid; i < NHh*SNB; i += TTHR){
      int h = i / SNB, cc = i % SNB;
      s_mxp[h][cc] = g_mx[(cc*NB + b)*MH + q0 + h];
    }
    __syncthreads();
    if (tid < NHh){
      float mm = -1e30f;
      for (int cc = 0; cc < SNB; cc++) mm = fmaxf(mm, s_mxp[tid][cc]);
      s_m[tid] = mm;
    }
    __syncthreads();
    for (int i = tid; i < NHh*SNB; i += TTHR){
      int h = i / SNB, cc = i % SNB;
      s_scale[h][cc] = __expf(s_mxp[h][cc] - s_m[h]);
    }
    __syncthreads();
    if (tid < NHh){
      float dd = 0.f;
      for (int cc = 0; cc < SNB; cc++)
        dd += g_denp[(cc*NB + b)*MH + q0 + tid] * s_scale[tid][cc];
      s_inv[tid] = 1.f/dd;
    }
    __syncthreads();
    for (int i = tid; i < 640; i += TTHR){
      int h = i >> 6, ep = i & 63;
      const float* base = g_wfp + (size_t)(q0 + h)*EE + es*128 + ep*2;
      float a0 = 0.f, a1 = 0.f;
      #pragma unroll 3
      for (int cc = 0; cc < SNB; cc++){
        float sc = s_scale[h][cc];
        float2 v2 = *(const float2*)(base + (size_t)(cc*NB + b)*MH*EE);
        a0 = fmaf(sc, v2.x, a0); a1 = fmaf(sc, v2.y, a1);
      }
      float inv = s_inv[h];
      s_wf[h][ep*2]   = a0*inv;
      s_wf[h][ep*2+1] = a1*inv;
    }
    __syncthreads();
    for (int col = tid; col < HID; col += TTHR){
      const float* v = s_wf[col >> 6];
      const float* w = Wv + (size_t)(es*128)*HID + col;
      float a0=0.f,a1=0.f,a2=0.f,a3=0.f;
      #pragma unroll 4
      for (int e = 0; e < 128; e += 4){
        a0 = fmaf(v[e+0], w[(size_t)(e+0)*HID], a0);
        a1 = fmaf(v[e+1], w[(size_t)(e+1)*HID], a1);
        a2 = fmaf(v[e+2], w[(size_t)(e+2)*HID], a2);
        a3 = fmaf(v[e+3], w[(size_t)(e+3)*HID], a3);
      }
      g_pp[((size_t)es*8 + bm)*HID + col] = (a0+a1)+(a2+a3);
    }
  }

  gsync();

  // ======== phase C: LN + class projection (blocks 0..67) ========
  if (blk < 68){
    float* s_a = (float*)dyn;
    float* s_v = (float*)(dyn + 2560);
    float* red = (float*)(dyn + 5120);
    float (*s_r)[32][2] = (float(*)[32][2])(dyn + 7168);
    int ct = blk / NB, b2 = blk % NB;
    #pragma unroll
    for (int m = 0; m < 2; m++){
      int bm = b2*2 + m;
      float av[2]; float psum = 0.f;
      #pragma unroll
      for (int k = 0; k < 2; k++){
        int col = tid + k*TTHR;
        float a = 0.f;
        if (col < HID){
          a = bv[col];
          #pragma unroll
          for (int es = 0; es < 4; es++) a += g_pp[((size_t)es*8 + bm)*HID + col];
        }
        av[k] = a; psum += a;
      }
      red[tid] = psum; __syncthreads();
      for (int s = 256; s; s >>= 1){ if (tid < s) red[tid] += red[tid+s]; __syncthreads(); }
      float mean = red[0] * (1.f/HID); __syncthreads();
      float pvar = 0.f;
      #pragma unroll
      for (int k = 0; k < 2; k++){
        int col = tid + k*TTHR;
        if (col < HID){ float d = av[k]-mean; pvar += d*d; }
      }
      red[tid] = pvar; __syncthreads();
      for (int s = 256; s; s >>= 1){ if (tid < s) red[tid] += red[tid+s]; __syncthreads(); }
      float inv = rsqrtf(red[0]*(1.f/HID) + 1e-5f); __syncthreads();
      float* dst = m ? s_v : s_a;
      #pragma unroll
      for (int k = 0; k < 2; k++){
        int col = tid + k*TTHR;
        if (col < HID) dst[col] = (av[k]-mean)*inv*lng[col] + lnb[col];
      }
      __syncthreads();
    }
    int lane = tid & 31, w = tid >> 5;
    int c = ct*32 + lane;
    float aa = 0.f, avv = 0.f;
    if (c < NC){
      const float* wa = Wap + (size_t)(w*40)*NC + c;
      const float* wv = Wvp + (size_t)(w*40)*NC + c;
      #pragma unroll 4
      for (int j = 0; j < 40; j++){
        int e = w*40 + j;
        aa  = fmaf(s_a[e], wa[(size_t)j*NC], aa);
        avv = fmaf(s_v[e], wv[(size_t)j*NC], avv);
      }
    }
    s_r[w][lane][0] = aa;
    s_r[w][lane][1] = avv;
    __syncthreads();
    if (tid < 32){
      float a = 0.f, v = 0.f;
      #pragma unroll
      for (int g = 0; g < 16; g++){ a += s_r[g][tid][0]; v += s_r[g][tid][1]; }
      int c2 = ct*32 + tid;
      if (c2 < NC)
        out[(size_t)b2*NC + c2] = 0.5f*((a + bap[c2]) + (v + bvp[c2]));
    }
  }
}

// ---------------- launch ----------------
extern "C" void kernel_launch(void* const* d_in, const int* in_sizes, int n_in,
                              void* d_out, int out_size){
  const float* aud  = (const float*)d_in[0];
  const float* vid  = (const float*)d_in[1];
  const float* atok = (const float*)d_in[2];
  const float* vtok = (const float*)d_in[3];
  const float* btk  = (const float*)d_in[4];
  const float* Wk   = (const float*)d_in[5];
  const float* bk   = (const float*)d_in[6];
  const float* Wq   = (const float*)d_in[7];
  const float* bq   = (const float*)d_in[8];
  const float* Wv   = (const float*)d_in[9];
  const float* bv   = (const float*)d_in[10];
  const float* lng  = (const float*)d_in[11];
  const float* lnb  = (const float*)d_in[12];
  const float* Wap  = (const float*)d_in[13];
  const float* bap  = (const float*)d_in[14];
  const float* Wvp  = (const float*)d_in[15];
  const float* bvp  = (const float*)d_in[16];
  float* out = (float*)d_out;

  const int ALL_SMEM = 56832;
  cudaFuncSetAttribute(k_all, cudaFuncAttributeMaxDynamicSharedMemorySize, ALL_SMEM);

  k_all<<<GRIDT, TTHR, ALL_SMEM>>>(aud, vid, atok, vtok, btk,
                                   Wk, bk, Wq, bq, Wv, bv, lng, lnb,
                                   Wap, bap, Wvp, bvp, out);
}

// round 12
// speedup vs baseline: 1.0948x; 1.0948x over previous
#include <cuda_runtime.h>
#include <math.h>
#include <stdint.h>

#define NB    4
#define LSEQ  2054
#define LSEQT 2080
#define EE    512
#define HID   640
#define NHh   10
#define NC    527
#define MH    20
#define SNT   64
#define SNB   33
#define ETIL  16
#define NTIL  9
#define FEAT_BLKS (ETIL*NTIL*NB)   // 576
#define GRIDT (SNB*NB)             // 132 tail blocks, 1/SM
#define TTHR  512

typedef unsigned long long u64;

// ---------------- device scratch ----------------
__device__ __align__(128) float g_feats [NB*LSEQ*EE];
__device__ __align__(128) float g_featsT[NB*EE*LSEQT];
__device__ u64   g_kq2[NB*256*MH];
__device__ float g_cb[NB*MH];
__device__ float g_mx  [SNB*NB*MH];
__device__ float g_denp[SNB*NB*MH];
__device__ float g_wfp [SNB*NB*MH*EE];
__device__ float g_pp[4*8*HID];
__device__ unsigned g_barc = 0;
__device__ volatile unsigned g_gen = 0;

// ---------------- grid barrier (all GRIDT blocks co-resident) -------------
__device__ __forceinline__ void gsync(){
  __syncthreads();
  if (threadIdx.x == 0){
    __threadfence();
    unsigned gen = g_gen;
    unsigned arrived = atomicAdd(&g_barc, 1u) + 1u;
    if (arrived % GRIDT == 0u){
      __threadfence();
      g_gen = gen + 1u;
    } else {
      while (g_gen == gen) { __nanosleep(64); }
    }
    __threadfence();
  }
  __syncthreads();
}

// ---------------- packed f32x2 helpers ----------------
__device__ __forceinline__ u64 pk2(float x, float y){
  u64 r; asm("mov.b64 %0,{%1,%2};" : "=l"(r) : "f"(x), "f"(y)); return r;
}
__device__ __forceinline__ float2 upk2(u64 v){
  float2 r; asm("mov.b64 {%0,%1},%2;" : "=f"(r.x), "=f"(r.y) : "l"(v)); return r;
}
__device__ __forceinline__ void fma2(u64 &d, u64 a, u64 b){
  asm("fma.rn.f32x2 %0,%1,%2,%0;" : "+l"(d) : "l"(a), "l"(b));
}
__device__ __forceinline__ u64 add2(u64 a, u64 b){
  u64 r; asm("add.rn.f32x2 %0,%1,%2;" : "=l"(r) : "l"(a), "l"(b)); return r;
}

__device__ __forceinline__ const float* row_src(int b, int n,
    const float* aud, const float* vid, const float* atok,
    const float* vtok, const float* btk){
  if (n < 1024)  return aud + ((size_t)b*1024 + n)*EE;
  if (n == 1024) return atok;
  if (n < 1029)  return btk + (size_t)(n-1025)*EE;
  if (n < 2053)  return vid + ((size_t)b*1024 + (n-1029))*EE;
  return vtok;
}

__device__ __forceinline__ float pe_val(int n, int e){
  float f = __expf(-(float)(e & ~1) * (9.210340371976184f/512.0f));
  float a = (float)n * f;
  float q = rintf(a * 0.15915494309189535f);
  a = fmaf(q, -6.2831855f, a);
  a = fmaf(q, 1.7484556e-7f, a);
  float sn, cs; __sincosf(a, &sn, &cs);
  return (e & 1) ? cs : sn;
}

// ================ K1: prep = feats/featsT (rotation recurrence) + kq =======
__global__ void __launch_bounds__(256) k_prep(
    const float* __restrict__ aud, const float* __restrict__ vid,
    const float* __restrict__ atok, const float* __restrict__ vtok,
    const float* __restrict__ btk,
    const float* __restrict__ Wk, const float* __restrict__ bk,
    const float* __restrict__ Wq, const float* __restrict__ bq){
  int blk = blockIdx.x;
  int tid = threadIdx.x;
  if (blk < FEAT_BLKS){
    __shared__ float s_t[256][33];
    int et = blk % ETIL;
    int nt = (blk / ETIL) % NTIL;
    int bz = blk / (ETIL*NTIL);
    int lane = tid & 31, w = tid >> 5;
    int e = et*32 + lane;
    bool odd = e & 1;
    float f = __expf(-(float)(e & ~1) * (9.210340371976184f/512.0f));
    int n0 = nt*256 + w*32;
    float a = (float)n0 * f;
    float qr = rintf(a * 0.15915494309189535f);
    a = fmaf(qr, -6.2831855f, a);
    a = fmaf(qr, 1.7484556e-7f, a);
    float sn, cs; __sincosf(a, &sn, &cs);
    float sf, cf; __sincosf(f, &sf, &cf);
    #pragma unroll 4
    for (int j = 0; j < 32; j++){
      int n = n0 + j;
      float v = 0.f;
      if (n < LSEQ){
        const float* src = row_src(bz, n, aud, vid, atok, vtok, btk);
        v = src[e] + (odd ? cs : sn);
        g_feats[((size_t)bz*LSEQ + n)*EE + e] = v;
      }
      s_t[w*32 + j][lane] = v;
      float sn2 = fmaf(sn, cf,  cs*sf);
      float cs2 = fmaf(cs, cf, -sn*sf);
      sn = sn2; cs = cs2;
    }
    __syncthreads();
    for (int ee = w; ee < 32; ee += 8){
      #pragma unroll
      for (int k = 0; k < 8; k++){
        int nl = lane + 32*k;
        int n = nt*256 + nl;
        if (n < LSEQ)
          g_featsT[((size_t)bz*EE + et*32 + ee)*LSEQT + n] = s_t[nl][ee];
      }
    }
  } else {
    __shared__ float sf[EE];
    __shared__ float spart[4][64];
    __shared__ float kk[64];
    int blk2 = blk - FEAT_BLKS;
    int b = blk2 / MH, mh = blk2 % MH, m = mh / NHh, h = mh % NHh;
    int nrow = m ? 1029 : 0;
    const float* src = m ? (vid + (size_t)b*1024*EE) : (aud + (size_t)b*1024*EE);
    for (int e = tid; e < EE; e += 256)
      sf[e] = src[e] + pe_val(nrow, e);
    __syncthreads();
    {
      int col = tid & 63, eg = tid >> 6;
      const float* w = Wk + h*64 + col;
      float p = 0.f;
      #pragma unroll 4
      for (int e = eg*128; e < eg*128 + 128; e++)
        p = fmaf(sf[e], w[(size_t)e*HID], p);
      spart[eg][col] = p;
    }
    __syncthreads();
    if (tid < 64)
      kk[tid] = bk[h*64 + tid] + ((spart[0][tid] + spart[1][tid]) +
                                  (spart[2][tid] + spart[3][tid]));
    __syncthreads();
    if (tid == 0){
      float s2 = 0.f;
      for (int d = 0; d < 64; d++) s2 += kk[d]*bq[h*64 + d];
      g_cb[blk2] = s2;
    }
    int e0 = tid*2;
    const float4* w0 = (const float4*)(Wq + (size_t)e0*HID + h*64);
    const float4* w1 = (const float4*)(Wq + (size_t)(e0+1)*HID + h*64);
    float r0 = 0.f, r1 = 0.f;
    #pragma unroll
    for (int d4 = 0; d4 < 16; d4++){
      float4 a = w0[d4], c = w1[d4];
      float k0 = kk[4*d4], k1 = kk[4*d4+1], k2 = kk[4*d4+2], k3 = kk[4*d4+3];
      r0 = fmaf(k0,a.x, fmaf(k1,a.y, fmaf(k2,a.z, fmaf(k3,a.w, r0))));
      r1 = fmaf(k0,c.x, fmaf(k1,c.y, fmaf(k2,c.z, fmaf(k3,c.w, r1))));
    }
    g_kq2[((size_t)b*256 + tid)*MH + mh] = pk2(r0, r1);
  }
}

// ================ K2: tail (512 thr, 1 blk/SM) ============================
// dyn smem 56,320 B:
//   [0,40960)      s_kq u64[256][20]  -> overlay s_part f[8][64][20] -> s_comb u64[256][20]
//   [40960,46080)  s_sc  f[64][20]
//   [46080,56320)  s_p   u64[64][20]
__global__ void __launch_bounds__(TTHR, 1) k_tail(
    const float* __restrict__ Wv,  const float* __restrict__ bv,
    const float* __restrict__ lng, const float* __restrict__ lnb,
    const float* __restrict__ Wap, const float* __restrict__ bap,
    const float* __restrict__ Wvp, const float* __restrict__ bvp,
    float* __restrict__ out){
  extern __shared__ __align__(16) char dyn[];
  int tid = threadIdx.x, blk = blockIdx.x;

  // ======== phase A: attention ========
  {
    u64*  s_kq = (u64*)dyn;
    float (*s_part)[SNT][MH] = (float(*)[SNT][MH])dyn;
    float (*s_sc)[MH]        = (float(*)[MH])(dyn + 40960);
    u64   (*s_p)[MH]         = (u64(*)[MH])(dyn + 46080);
    u64*  s_comb             = (u64*)dyn;
    __shared__ float s_cb[MH], s_mx[MH];
    int c = blk % SNB, b = blk / SNB;
    {
      const u64* src = g_kq2 + (size_t)b*256*MH;
      for (int i = tid; i < 256*MH; i += TTHR) s_kq[i] = src[i];
    }
    if (tid < MH) s_cb[tid] = g_cb[b*MH + tid];
    __syncthreads();
    int slot = tid & 63, esub = tid >> 6;      // esub 0..7, 64 e per chunk
    int nbase = c*SNT;
    int n = nbase + slot; if (n > LSEQ-1) n = LSEQ-1;
    const float* ft = g_featsT + ((size_t)b*EE + esub*64)*LSEQT + n;
    const u64* kqp = s_kq + (size_t)(esub*32)*MH;
    u64 acc[MH];
    #pragma unroll
    for (int q = 0; q < MH; q++) acc[q] = 0ull;
    #pragma unroll 4
    for (int ep = 0; ep < 32; ep++){
      float f0 = ft[(size_t)(2*ep  )*LSEQT];
      float f1 = ft[(size_t)(2*ep+1)*LSEQT];
      u64 f2 = pk2(f0, f1);
      const ulonglong2* kp2 = (const ulonglong2*)(kqp + (size_t)ep*MH);
      #pragma unroll
      for (int q2 = 0; q2 < 10; q2++){
        ulonglong2 kk2 = kp2[q2];
        fma2(acc[2*q2  ], f2, kk2.x);
        fma2(acc[2*q2+1], f2, kk2.y);
      }
    }
    __syncthreads();
    #pragma unroll
    for (int q = 0; q < MH; q++){
      float2 v2 = upk2(acc[q]);
      s_part[esub][slot][q] = v2.x + v2.y;
    }
    __syncthreads();
    for (int i = tid; i < SNT*MH; i += TTHR){
      int nl = i / MH, q = i % MH;
      float s = ((s_part[0][nl][q] + s_part[1][nl][q]) +
                 (s_part[2][nl][q] + s_part[3][nl][q])) +
                ((s_part[4][nl][q] + s_part[5][nl][q]) +
                 (s_part[6][nl][q] + s_part[7][nl][q]));
      s = (s + s_cb[q]) * 0.125f;
      s_sc[nl][q] = (nbase + nl < LSEQ) ? s : -1e30f;
    }
    __syncthreads();
    if (tid < 160){
      int q = tid >> 3, j = tid & 7;
      float mloc = -1e30f;
      #pragma unroll
      for (int nl = j*8; nl < j*8 + 8; nl++) mloc = fmaxf(mloc, s_sc[nl][q]);
      mloc = fmaxf(mloc, __shfl_xor_sync(0xffffffffu, mloc, 1));
      mloc = fmaxf(mloc, __shfl_xor_sync(0xffffffffu, mloc, 2));
      mloc = fmaxf(mloc, __shfl_xor_sync(0xffffffffu, mloc, 4));
      if (j == 0){ s_mx[q] = mloc; g_mx[(c*NB + b)*MH + q] = mloc; }
    }
    __syncthreads();
    for (int i = tid; i < SNT*MH; i += TTHR){
      int nl = i / MH, q = i % MH;
      float p = __expf(s_sc[nl][q] - s_mx[q]);
      s_p[nl][q] = pk2(p, p);
    }
    __syncthreads();
    if (tid < 160){
      int q = tid >> 3, j = tid & 7;
      float d = 0.f;
      #pragma unroll
      for (int nl = j*8; nl < j*8 + 8; nl++) d += *(const float*)&s_p[nl][q];
      d += __shfl_xor_sync(0xffffffffu, d, 1);
      d += __shfl_xor_sync(0xffffffffu, d, 2);
      d += __shfl_xor_sync(0xffffffffu, d, 4);
      if (j == 0) g_denp[(c*NB + b)*MH + q] = d;
    }
    // ---- weighted feats: 2 token-halves x 256 e-pairs ----
    int half = tid >> 8, ep0 = tid & 255;
    int e0 = ep0*2;
    int nv = LSEQ - nbase; if (nv > SNT) nv = SNT;
    int nlo = half*32;
    int nhi = nv < (half+1)*32 ? nv : (half+1)*32;
    const float* fb = g_feats + ((size_t)b*LSEQ + nbase)*EE + e0;
    u64 acc2[MH];
    #pragma unroll
    for (int q = 0; q < MH; q++) acc2[q] = 0ull;
    #pragma unroll 2
    for (int nl = nlo; nl < nhi; nl++){
      u64 f = *(const u64*)(fb + (size_t)nl*EE);
      const ulonglong2* pp2 = (const ulonglong2*)s_p[nl];
      #pragma unroll
      for (int q2 = 0; q2 < 10; q2++){
        ulonglong2 pk = pp2[q2];
        fma2(acc2[2*q2  ], pk.x, f);
        fma2(acc2[2*q2+1], pk.y, f);
      }
    }
    if (half == 1){
      #pragma unroll
      for (int q = 0; q < MH; q++) s_comb[ep0*MH + q] = acc2[q];
    }
    __syncthreads();
    if (half == 0){
      float* dst = g_wfp + ((size_t)(c*NB + b)*MH)*EE + e0;
      #pragma unroll
      for (int q = 0; q < MH; q++){
        float2 v2 = upk2(add2(acc2[q], s_comb[ep0*MH + q]));
        *(float2*)(dst + (size_t)q*EE) = v2;
      }
    }
  }

  gsync();

  // ======== phase B: flash-combine + partial Wv proj (blocks 0..31) ========
  if (blk < 32){
    float (*s_mxp)[SNB+1]   = (float(*)[SNB+1])dyn;
    float (*s_scale)[SNB+1] = (float(*)[SNB+1])(dyn + 1360);
    float* s_m   = (float*)(dyn + 2720);
    float* s_inv = (float*)(dyn + 2784);
    float (*s_wf)[128] = (float(*)[128])(dyn + 2848);
    int bm = blk >> 2, es = blk & 3;
    int b = bm >> 1, m = bm & 1, q0 = m*NHh;
    for (int i = tid; i < NHh*SNB; i += TTHR){
      int h = i / SNB, cc = i % SNB;
      s_mxp[h][cc] = g_mx[(cc*NB + b)*MH + q0 + h];
    }
    __syncthreads();
    if (tid < NHh){
      float mm = -1e30f;
      for (int cc = 0; cc < SNB; cc++) mm = fmaxf(mm, s_mxp[tid][cc]);
      s_m[tid] = mm;
    }
    __syncthreads();
    for (int i = tid; i < NHh*SNB; i += TTHR){
      int h = i / SNB, cc = i % SNB;
      s_scale[h][cc] = __expf(s_mxp[h][cc] - s_m[h]);
    }
    __syncthreads();
    if (tid < NHh){
      float dd = 0.f;
      for (int cc = 0; cc < SNB; cc++)
        dd += g_denp[(cc*NB + b)*MH + q0 + tid] * s_scale[tid][cc];
      s_inv[tid] = 1.f/dd;
    }
    __syncthreads();
    for (int i = tid; i < 640; i += TTHR){
      int h = i >> 6, ep = i & 63;
      const float* base = g_wfp + (size_t)(q0 + h)*EE + es*128 + ep*2;
      float a0 = 0.f, a1 = 0.f;
      #pragma unroll 3
      for (int cc = 0; cc < SNB; cc++){
        float sc = s_scale[h][cc];
        float2 v2 = *(const float2*)(base + (size_t)(cc*NB + b)*MH*EE);
        a0 = fmaf(sc, v2.x, a0); a1 = fmaf(sc, v2.y, a1);
      }
      float inv = s_inv[h];
      s_wf[h][ep*2]   = a0*inv;
      s_wf[h][ep*2+1] = a1*inv;
    }
    __syncthreads();
    for (int col = tid; col < HID; col += TTHR){
      const float* v = s_wf[col >> 6];
      const float* w = Wv + (size_t)(es*128)*HID + col;
      float a0=0.f,a1=0.f,a2=0.f,a3=0.f;
      #pragma unroll 4
      for (int e = 0; e < 128; e += 4){
        a0 = fmaf(v[e+0], w[(size_t)(e+0)*HID], a0);
        a1 = fmaf(v[e+1], w[(size_t)(e+1)*HID], a1);
        a2 = fmaf(v[e+2], w[(size_t)(e+2)*HID], a2);
        a3 = fmaf(v[e+3], w[(size_t)(e+3)*HID], a3);
      }
      g_pp[((size_t)es*8 + bm)*HID + col] = (a0+a1)+(a2+a3);
    }
  }

  gsync();

  // ======== phase C: LN + class projection (blocks 0..67) ========
  if (blk < 68){
    float* s_a = (float*)dyn;
    float* s_v = (float*)(dyn + 2560);
    float* red = (float*)(dyn + 5120);
    float (*s_r)[32][2] = (float(*)[32][2])(dyn + 7168);
    int ct = blk / NB, b2 = blk % NB;
    #pragma unroll
    for (int m = 0; m < 2; m++){
      int bm = b2*2 + m;
      float av[2]; float psum = 0.f;
      #pragma unroll
      for (int k = 0; k < 2; k++){
        int col = tid + k*TTHR;
        float a = 0.f;
        if (col < HID){
          a = bv[col];
          #pragma unroll
          for (int es = 0; es < 4; es++) a += g_pp[((size_t)es*8 + bm)*HID + col];
        }
        av[k] = a; psum += a;
      }
      red[tid] = psum; __syncthreads();
      for (int s = 256; s; s >>= 1){ if (tid < s) red[tid] += red[tid+s]; __syncthreads(); }
      float mean = red[0] * (1.f/HID); __syncthreads();
      float pvar = 0.f;
      #pragma unroll
      for (int k = 0; k < 2; k++){
        int col = tid + k*TTHR;
        if (col < HID){ float d = av[k]-mean; pvar += d*d; }
      }
      red[tid] = pvar; __syncthreads();
      for (int s = 256; s; s >>= 1){ if (tid < s) red[tid] += red[tid+s]; __syncthreads(); }
      float inv = rsqrtf(red[0]*(1.f/HID) + 1e-5f); __syncthreads();
      float* dst = m ? s_v : s_a;
      #pragma unroll
      for (int k = 0; k < 2; k++){
        int col = tid + k*TTHR;
        if (col < HID) dst[col] = (av[k]-mean)*inv*lng[col] + lnb[col];
      }
      __syncthreads();
    }
    int lane = tid & 31, w = tid >> 5;
    int c = ct*32 + lane;
    float aa = 0.f, avv = 0.f;
    if (c < NC){
      const float* wa = Wap + (size_t)(w*40)*NC + c;
      const float* wv = Wvp + (size_t)(w*40)*NC + c;
      #pragma unroll 4
      for (int j = 0; j < 40; j++){
        int e = w*40 + j;
        aa  = fmaf(s_a[e], wa[(size_t)j*NC], aa);
        avv = fmaf(s_v[e], wv[(size_t)j*NC], avv);
      }
    }
    s_r[w][lane][0] = aa;
    s_r[w][lane][1] = avv;
    __syncthreads();
    if (tid < 32){
      float a = 0.f, v = 0.f;
      #pragma unroll
      for (int g = 0; g < 16; g++){ a += s_r[g][tid][0]; v += s_r[g][tid][1]; }
      int c2 = ct*32 + tid;
      if (c2 < NC)
        out[(size_t)b2*NC + c2] = 0.5f*((a + bap[c2]) + (v + bvp[c2]));
    }
  }
}

// ---------------- launch ----------------
extern "C" void kernel_launch(void* const* d_in, const int* in_sizes, int n_in,
                              void* d_out, int out_size){
  const float* aud  = (const float*)d_in[0];
  const float* vid  = (const float*)d_in[1];
  const float* atok = (const float*)d_in[2];
  const float* vtok = (const float*)d_in[3];
  const float* btk  = (const float*)d_in[4];
  const float* Wk   = (const float*)d_in[5];
  const float* bk   = (const float*)d_in[6];
  const float* Wq   = (const float*)d_in[7];
  const float* bq   = (const float*)d_in[8];
  const float* Wv   = (const float*)d_in[9];
  const float* bv   = (const float*)d_in[10];
  const float* lng  = (const float*)d_in[11];
  const float* lnb  = (const float*)d_in[12];
  const float* Wap  = (const float*)d_in[13];
  const float* bap  = (const float*)d_in[14];
  const float* Wvp  = (const float*)d_in[15];
  const float* bvp  = (const float*)d_in[16];
  float* out = (float*)d_out;

  const int TAIL_SMEM = 56320;
  cudaFuncSetAttribute(k_tail, cudaFuncAttributeMaxDynamicSharedMemorySize, TAIL_SMEM);

  k_prep<<<FEAT_BLKS + NB*MH, 256>>>(aud, vid, atok, vtok, btk, Wk, bk, Wq, bq);
  k_tail<<<GRIDT, TTHR, TAIL_SMEM>>>(Wv, bv, lng, lnb, Wap, bap, Wvp, bvp, out);
}

// round 13
// speedup vs baseline: 1.1942x; 1.0907x over previous
#include <cuda_runtime.h>
#include <math.h>
#include <stdint.h>

#define NB    4
#define LSEQ  2054
#define LSEQT 2080
#define EE    512
#define HID   640
#define NHh   10
#define NC    527
#define MH    20
#define SNT   64
#define SNB   33
#define ETIL  16
#define NTIL  9
#define FEAT_BLKS (ETIL*NTIL*NB)   // 576
#define GRIDT (SNB*NB)             // 132 tail blocks, 1/SM
#define TTHR  512

typedef unsigned long long u64;

// ---------------- device scratch ----------------
// e-pair-interleaved feats+pe: row p=e/2 (256 rows per batch), float2 {e,e+1}
__device__ __align__(128) float2 g_ft2[NB*256*LSEQT];
__device__ u64   g_kq2[NB*256*MH];
__device__ float g_cb[NB*MH];
__device__ float g_mx  [SNB*NB*MH];
__device__ float g_denp[SNB*NB*MH];
__device__ float g_wfp [SNB*NB*MH*EE];
__device__ float g_pp[4*8*HID];
__device__ unsigned g_barc = 0;
__device__ volatile unsigned g_gen = 0;

// ---------------- grid barrier (all GRIDT blocks co-resident) -------------
__device__ __forceinline__ void gsync(){
  __syncthreads();
  if (threadIdx.x == 0){
    __threadfence();
    unsigned gen = g_gen;
    unsigned arrived = atomicAdd(&g_barc, 1u) + 1u;
    if (arrived % GRIDT == 0u){
      __threadfence();
      g_gen = gen + 1u;
    } else {
      while (g_gen == gen) { __nanosleep(64); }
    }
    __threadfence();
  }
  __syncthreads();
}

// ---------------- packed f32x2 helpers ----------------
__device__ __forceinline__ u64 pk2(float x, float y){
  u64 r; asm("mov.b64 %0,{%1,%2};" : "=l"(r) : "f"(x), "f"(y)); return r;
}
__device__ __forceinline__ float2 upk2(u64 v){
  float2 r; asm("mov.b64 {%0,%1},%2;" : "=f"(r.x), "=f"(r.y) : "l"(v)); return r;
}
__device__ __forceinline__ void fma2(u64 &d, u64 a, u64 b){
  asm("fma.rn.f32x2 %0,%1,%2,%0;" : "+l"(d) : "l"(a), "l"(b));
}
__device__ __forceinline__ u64 add2(u64 a, u64 b){
  u64 r; asm("add.rn.f32x2 %0,%1,%2;" : "=l"(r) : "l"(a), "l"(b)); return r;
}

__device__ __forceinline__ const float* row_src(int b, int n,
    const float* aud, const float* vid, const float* atok,
    const float* vtok, const float* btk){
  if (n < 1024)  return aud + ((size_t)b*1024 + n)*EE;
  if (n == 1024) return atok;
  if (n < 1029)  return btk + (size_t)(n-1025)*EE;
  if (n < 2053)  return vid + ((size_t)b*1024 + (n-1029))*EE;
  return vtok;
}

__device__ __forceinline__ float pe_val(int n, int e){
  float f = __expf(-(float)(e & ~1) * (9.210340371976184f/512.0f));
  float a = (float)n * f;
  float q = rintf(a * 0.15915494309189535f);
  a = fmaf(q, -6.2831855f, a);
  a = fmaf(q, 1.7484556e-7f, a);
  float sn, cs; __sincosf(a, &sn, &cs);
  return (e & 1) ? cs : sn;
}

// ================ K1: prep = ft2 (rotation recurrence) + kq =======
__global__ void __launch_bounds__(256) k_prep(
    const float* __restrict__ aud, const float* __restrict__ vid,
    const float* __restrict__ atok, const float* __restrict__ vtok,
    const float* __restrict__ btk,
    const float* __restrict__ Wk, const float* __restrict__ bk,
    const float* __restrict__ Wq, const float* __restrict__ bq){
  int blk = blockIdx.x;
  int tid = threadIdx.x;
  if (blk < FEAT_BLKS){
    __shared__ float s_t[256][33];         // [n_local][e_lane]
    int et = blk % ETIL;
    int nt = (blk / ETIL) % NTIL;
    int bz = blk / (ETIL*NTIL);
    int lane = tid & 31, w = tid >> 5;
    int e = et*32 + lane;
    bool odd = e & 1;
    float f = __expf(-(float)(e & ~1) * (9.210340371976184f/512.0f));
    int n0 = nt*256 + w*32;
    float a = (float)n0 * f;
    float qr = rintf(a * 0.15915494309189535f);
    a = fmaf(qr, -6.2831855f, a);
    a = fmaf(qr, 1.7484556e-7f, a);
    float sn, cs; __sincosf(a, &sn, &cs);
    float sf, cf; __sincosf(f, &sf, &cf);
    #pragma unroll 4
    for (int j = 0; j < 32; j++){
      int n = n0 + j;
      float v = 0.f;
      if (n < LSEQ){
        const float* src = row_src(bz, n, aud, vid, atok, vtok, btk);
        v = src[e] + (odd ? cs : sn);
      }
      s_t[w*32 + j][lane] = v;
      float sn2 = fmaf(sn, cf,  cs*sf);
      float cs2 = fmaf(cs, cf, -sn*sf);
      sn = sn2; cs = cs2;
    }
    __syncthreads();
    // e-pair transposed write: row = et*16 + pe, coalesced along n
    for (int pe = w; pe < 16; pe += 8){
      #pragma unroll
      for (int k = 0; k < 8; k++){
        int nl = lane + 32*k;
        int n = nt*256 + nl;
        if (n < LSEQ){
          float2 v2 = make_float2(s_t[nl][2*pe], s_t[nl][2*pe+1]);
          g_ft2[((size_t)bz*256 + et*16 + pe)*LSEQT + n] = v2;
        }
      }
    }
  } else {
    __shared__ float sf[EE];
    __shared__ float spart[4][64];
    __shared__ float kk[64];
    int blk2 = blk - FEAT_BLKS;
    int b = blk2 / MH, mh = blk2 % MH, m = mh / NHh, h = mh % NHh;
    int nrow = m ? 1029 : 0;
    const float* src = m ? (vid + (size_t)b*1024*EE) : (aud + (size_t)b*1024*EE);
    for (int e = tid; e < EE; e += 256)
      sf[e] = src[e] + pe_val(nrow, e);
    __syncthreads();
    {
      int col = tid & 63, eg = tid >> 6;
      const float* w = Wk + h*64 + col;
      float p = 0.f;
      #pragma unroll 4
      for (int e = eg*128; e < eg*128 + 128; e++)
        p = fmaf(sf[e], w[(size_t)e*HID], p);
      spart[eg][col] = p;
    }
    __syncthreads();
    if (tid < 64)
      kk[tid] = bk[h*64 + tid] + ((spart[0][tid] + spart[1][tid]) +
                                  (spart[2][tid] + spart[3][tid]));
    __syncthreads();
    if (tid == 0){
      float s2 = 0.f;
      for (int d = 0; d < 64; d++) s2 += kk[d]*bq[h*64 + d];
      g_cb[blk2] = s2;
    }
    int e0 = tid*2;
    const float4* w0 = (const float4*)(Wq + (size_t)e0*HID + h*64);
    const float4* w1 = (const float4*)(Wq + (size_t)(e0+1)*HID + h*64);
    float r0 = 0.f, r1 = 0.f;
    #pragma unroll
    for (int d4 = 0; d4 < 16; d4++){
      float4 a = w0[d4], c = w1[d4];
      float k0 = kk[4*d4], k1 = kk[4*d4+1], k2 = kk[4*d4+2], k3 = kk[4*d4+3];
      r0 = fmaf(k0,a.x, fmaf(k1,a.y, fmaf(k2,a.z, fmaf(k3,a.w, r0))));
      r1 = fmaf(k0,c.x, fmaf(k1,c.y, fmaf(k2,c.z, fmaf(k3,c.w, r1))));
    }
    g_kq2[((size_t)b*256 + tid)*MH + mh] = pk2(r0, r1);
  }
}

// ================ K2: tail (512 thr, 1 blk/SM) ============================
// dyn smem 56,320 B:
//   [0,40960)      s_kq u64[256][20]  -> overlay s_part f[8][64][20] -> s_comb u64[256][20]
//   [40960,46080)  s_sc  f[64][20]
//   [46080,56320)  s_p   u64[64][20]
__global__ void __launch_bounds__(TTHR, 1) k_tail(
    const float* __restrict__ Wv,  const float* __restrict__ bv,
    const float* __restrict__ lng, const float* __restrict__ lnb,
    const float* __restrict__ Wap, const float* __restrict__ bap,
    const float* __restrict__ Wvp, const float* __restrict__ bvp,
    float* __restrict__ out){
  extern __shared__ __align__(16) char dyn[];
  int tid = threadIdx.x, blk = blockIdx.x;

  // ======== phase A: attention ========
  {
    u64*  s_kq = (u64*)dyn;
    float (*s_part)[SNT][MH] = (float(*)[SNT][MH])dyn;
    float (*s_sc)[MH]        = (float(*)[MH])(dyn + 40960);
    u64   (*s_p)[MH]         = (u64(*)[MH])(dyn + 46080);
    u64*  s_comb             = (u64*)dyn;
    __shared__ float s_cb[MH], s_mx[MH];
    int c = blk % SNB, b = blk / SNB;
    {
      const u64* src = g_kq2 + (size_t)b*256*MH;
      for (int i = tid; i < 256*MH; i += TTHR) s_kq[i] = src[i];
    }
    if (tid < MH) s_cb[tid] = g_cb[b*MH + tid];
    __syncthreads();
    int slot = tid & 63, esub = tid >> 6;      // esub 0..7 = 32 e-pairs each
    int nbase = c*SNT;
    int n = nbase + slot; if (n > LSEQ-1) n = LSEQ-1;
    const float2* ft = g_ft2 + ((size_t)b*256 + esub*32)*LSEQT + n;
    const u64* kqp = s_kq + (size_t)(esub*32)*MH;
    u64 acc[MH];
    #pragma unroll
    for (int q = 0; q < MH; q++) acc[q] = 0ull;
    #pragma unroll 4
    for (int ep = 0; ep < 32; ep++){
      u64 f2 = *(const u64*)(ft + (size_t)ep*LSEQT);
      const ulonglong2* kp2 = (const ulonglong2*)(kqp + (size_t)ep*MH);
      #pragma unroll
      for (int q2 = 0; q2 < 10; q2++){
        ulonglong2 kk2 = kp2[q2];
        fma2(acc[2*q2  ], f2, kk2.x);
        fma2(acc[2*q2+1], f2, kk2.y);
      }
    }
    __syncthreads();
    #pragma unroll
    for (int q = 0; q < MH; q++){
      float2 v2 = upk2(acc[q]);
      s_part[esub][slot][q] = v2.x + v2.y;
    }
    __syncthreads();
    for (int i = tid; i < SNT*MH; i += TTHR){
      int nl = i / MH, q = i % MH;
      float s = ((s_part[0][nl][q] + s_part[1][nl][q]) +
                 (s_part[2][nl][q] + s_part[3][nl][q])) +
                ((s_part[4][nl][q] + s_part[5][nl][q]) +
                 (s_part[6][nl][q] + s_part[7][nl][q]));
      s = (s + s_cb[q]) * 0.125f;
      s_sc[nl][q] = (nbase + nl < LSEQ) ? s : -1e30f;
    }
    __syncthreads();
    if (tid < 160){
      int q = tid >> 3, j = tid & 7;
      float mloc = -1e30f;
      #pragma unroll
      for (int nl = j*8; nl < j*8 + 8; nl++) mloc = fmaxf(mloc, s_sc[nl][q]);
      mloc = fmaxf(mloc, __shfl_xor_sync(0xffffffffu, mloc, 1));
      mloc = fmaxf(mloc, __shfl_xor_sync(0xffffffffu, mloc, 2));
      mloc = fmaxf(mloc, __shfl_xor_sync(0xffffffffu, mloc, 4));
      if (j == 0){ s_mx[q] = mloc; g_mx[(c*NB + b)*MH + q] = mloc; }
    }
    __syncthreads();
    for (int i = tid; i < SNT*MH; i += TTHR){
      int nl = i / MH, q = i % MH;
      float p = __expf(s_sc[nl][q] - s_mx[q]);
      s_p[nl][q] = pk2(p, p);
    }
    __syncthreads();
    if (tid < 160){
      int q = tid >> 3, j = tid & 7;
      float d = 0.f;
      #pragma unroll
      for (int nl = j*8; nl < j*8 + 8; nl++) d += *(const float*)&s_p[nl][q];
      d += __shfl_xor_sync(0xffffffffu, d, 1);
      d += __shfl_xor_sync(0xffffffffu, d, 2);
      d += __shfl_xor_sync(0xffffffffu, d, 4);
      if (j == 0) g_denp[(c*NB + b)*MH + q] = d;
    }
    // ---- weighted feats: 2 token-halves x 256 e-pairs (L1-hit reads) ----
    int half = tid >> 8, ep0 = tid & 255;
    int nv = LSEQ - nbase; if (nv > SNT) nv = SNT;
    int nlo = half*32;
    int nhi = nv < (half+1)*32 ? nv : (half+1)*32;
    const float2* fb2 = g_ft2 + ((size_t)b*256 + ep0)*LSEQT + nbase;
    u64 acc2[MH];
    #pragma unroll
    for (int q = 0; q < MH; q++) acc2[q] = 0ull;
    #pragma unroll 2
    for (int nl = nlo; nl < nhi; nl++){
      u64 f = *(const u64*)(fb2 + nl);
      const ulonglong2* pp2 = (const ulonglong2*)s_p[nl];
      #pragma unroll
      for (int q2 = 0; q2 < 10; q2++){
        ulonglong2 pk = pp2[q2];
        fma2(acc2[2*q2  ], pk.x, f);
        fma2(acc2[2*q2+1], pk.y, f);
      }
    }
    if (half == 1){
      #pragma unroll
      for (int q = 0; q < MH; q++) s_comb[ep0*MH + q] = acc2[q];
    }
    __syncthreads();
    if (half == 0){
      float* dst = g_wfp + ((size_t)(c*NB + b)*MH)*EE + ep0*2;
      #pragma unroll
      for (int q = 0; q < MH; q++){
        float2 v2 = upk2(add2(acc2[q], s_comb[ep0*MH + q]));
        *(float2*)(dst + (size_t)q*EE) = v2;
      }
    }
  }

  gsync();

  // ======== phase B: flash-combine + partial Wv proj (blocks 0..31) ========
  if (blk < 32){
    float (*s_mxp)[SNB+1]   = (float(*)[SNB+1])dyn;
    float (*s_scale)[SNB+1] = (float(*)[SNB+1])(dyn + 1360);
    float* s_m   = (float*)(dyn + 2720);
    float* s_inv = (float*)(dyn + 2784);
    float (*s_wf)[128] = (float(*)[128])(dyn + 2848);
    int bm = blk >> 2, es = blk & 3;
    int b = bm >> 1, m = bm & 1, q0 = m*NHh;
    for (int i = tid; i < NHh*SNB; i += TTHR){
      int h = i / SNB, cc = i % SNB;
      s_mxp[h][cc] = g_mx[(cc*NB + b)*MH + q0 + h];
    }
    __syncthreads();
    if (tid < NHh){
      float mm = -1e30f;
      for (int cc = 0; cc < SNB; cc++) mm = fmaxf(mm, s_mxp[tid][cc]);
      s_m[tid] = mm;
    }
    __syncthreads();
    for (int i = tid; i < NHh*SNB; i += TTHR){
      int h = i / SNB, cc = i % SNB;
      s_scale[h][cc] = __expf(s_mxp[h][cc] - s_m[h]);
    }
    __syncthreads();
    if (tid < NHh){
      float dd = 0.f;
      for (int cc = 0; cc < SNB; cc++)
        dd += g_denp[(cc*NB + b)*MH + q0 + tid] * s_scale[tid][cc];
      s_inv[tid] = 1.f/dd;
    }
    __syncthreads();
    for (int i = tid; i < 640; i += TTHR){
      int h = i >> 6, ep = i & 63;
      const float* base = g_wfp + (size_t)(q0 + h)*EE + es*128 + ep*2;
      float a0 = 0.f, a1 = 0.f;
      #pragma unroll 3
      for (int cc = 0; cc < SNB; cc++){
        float sc = s_scale[h][cc];
        float2 v2 = *(const float2*)(base + (size_t)(cc*NB + b)*MH*EE);
        a0 = fmaf(sc, v2.x, a0); a1 = fmaf(sc, v2.y, a1);
      }
      float inv = s_inv[h];
      s_wf[h][ep*2]   = a0*inv;
      s_wf[h][ep*2+1] = a1*inv;
    }
    __syncthreads();
    for (int col = tid; col < HID; col += TTHR){
      const float* v = s_wf[col >> 6];
      const float* w = Wv + (size_t)(es*128)*HID + col;
      float a0=0.f,a1=0.f,a2=0.f,a3=0.f;
      #pragma unroll 4
      for (int e = 0; e < 128; e += 4){
        a0 = fmaf(v[e+0], w[(size_t)(e+0)*HID], a0);
        a1 = fmaf(v[e+1], w[(size_t)(e+1)*HID], a1);
        a2 = fmaf(v[e+2], w[(size_t)(e+2)*HID], a2);
        a3 = fmaf(v[e+3], w[(size_t)(e+3)*HID], a3);
      }
      g_pp[((size_t)es*8 + bm)*HID + col] = (a0+a1)+(a2+a3);
    }
  }

  gsync();

  // ======== phase C: LN + class projection (blocks 0..67) ========
  if (blk < 68){
    float* s_a = (float*)dyn;
    float* s_v = (float*)(dyn + 2560);
    float* red = (float*)(dyn + 5120);
    float (*s_r)[32][2] = (float(*)[32][2])(dyn + 7168);
    int ct = blk / NB, b2 = blk % NB;
    #pragma unroll
    for (int m = 0; m < 2; m++){
      int bm = b2*2 + m;
      float av[2]; float psum = 0.f;
      #pragma unroll
      for (int k = 0; k < 2; k++){
        int col = tid + k*TTHR;
        float a = 0.f;
        if (col < HID){
          a = bv[col];
          #pragma unroll
          for (int es = 0; es < 4; es++) a += g_pp[((size_t)es*8 + bm)*HID + col];
        }
        av[k] = a; psum += a;
      }
      red[tid] = psum; __syncthreads();
      for (int s = 256; s; s >>= 1){ if (tid < s) red[tid] += red[tid+s]; __syncthreads(); }
      float mean = red[0] * (1.f/HID); __syncthreads();
      float pvar = 0.f;
      #pragma unroll
      for (int k = 0; k < 2; k++){
        int col = tid + k*TTHR;
        if (col < HID){ float d = av[k]-mean; pvar += d*d; }
      }
      red[tid] = pvar; __syncthreads();
      for (int s = 256; s; s >>= 1){ if (tid < s) red[tid] += red[tid+s]; __syncthreads(); }
      float inv = rsqrtf(red[0]*(1.f/HID) + 1e-5f); __syncthreads();
      float* dst = m ? s_v : s_a;
      #pragma unroll
      for (int k = 0; k < 2; k++){
        int col = tid + k*TTHR;
        if (col < HID) dst[col] = (av[k]-mean)*inv*lng[col] + lnb[col];
      }
      __syncthreads();
    }
    int lane = tid & 31, w = tid >> 5;
    int c = ct*32 + lane;
    float aa = 0.f, avv = 0.f;
    if (c < NC){
      const float* wa = Wap + (size_t)(w*40)*NC + c;
      const float* wv = Wvp + (size_t)(w*40)*NC + c;
      #pragma unroll 4
      for (int j = 0; j < 40; j++){
        int e = w*40 + j;
        aa  = fmaf(s_a[e], wa[(size_t)j*NC], aa);
        avv = fmaf(s_v[e], wv[(size_t)j*NC], avv);
      }
    }
    s_r[w][lane][0] = aa;
    s_r[w][lane][1] = avv;
    __syncthreads();
    if (tid < 32){
      float a = 0.f, v = 0.f;
      #pragma unroll
      for (int g = 0; g < 16; g++){ a += s_r[g][tid][0]; v += s_r[g][tid][1]; }
      int c2 = ct*32 + tid;
      if (c2 < NC)
        out[(size_t)b2*NC + c2] = 0.5f*((a + bap[c2]) + (v + bvp[c2]));
    }
  }
}

// ---------------- launch ----------------
extern "C" void kernel_launch(void* const* d_in, const int* in_sizes, int n_in,
                              void* d_out, int out_size){
  const float* aud  = (const float*)d_in[0];
  const float* vid  = (const float*)d_in[1];
  const float* atok = (const float*)d_in[2];
  const float* vtok = (const float*)d_in[3];
  const float* btk  = (const float*)d_in[4];
  const float* Wk   = (const float*)d_in[5];
  const float* bk   = (const float*)d_in[6];
  const float* Wq   = (const float*)d_in[7];
  const float* bq   = (const float*)d_in[8];
  const float* Wv   = (const float*)d_in[9];
  const float* bv   = (const float*)d_in[10];
  const float* lng  = (const float*)d_in[11];
  const float* lnb  = (const float*)d_in[12];
  const float* Wap  = (const float*)d_in[13];
  const float* bap  = (const float*)d_in[14];
  const float* Wvp  = (const float*)d_in[15];
  const float* bvp  = (const float*)d_in[16];
  float* out = (float*)d_out;

  const int TAIL_SMEM = 56320;
  cudaFuncSetAttribute(k_tail, cudaFuncAttributeMaxDynamicSharedMemorySize, TAIL_SMEM);

  k_prep<<<FEAT_BLKS + NB*MH, 256>>>(aud, vid, atok, vtok, btk, Wk, bk, Wq, bq);
  k_tail<<<GRIDT, TTHR, TAIL_SMEM>>>(Wv, bv, lng, lnb, Wap, bap, Wvp, bvp, out);
}